// round 14
// baseline (speedup 1.0000x reference)
#include <cuda_runtime.h>
#include <math.h>

// Problem constants
#define BB 64
#define SS 512
#define PD 300       // feature dim (=150 pairs = 75 pair-pairs, exact)
#define KK 50        // labels
#define RR 5
#define NROWS (BB*SS)        // 32768
#define BM 64                // rows per K1 block
#define XSS 300              // xs row stride in floats (1200B, 16B multiple)
#define NCH 8                // k3 pooling chunks per batch (measured best)

#define ROW_BYTES (PD*4)               // 1200
#define TOTAL_TX (BM*ROW_BYTES)        // 76800
#define CH_IMG 9600                    // floats per label-half image (38.4 KB)

// Scratch (device globals; no runtime allocation allowed)
__device__ __align__(16) float g_ch2[2*CH_IMG];     // two label-half B images
__device__ __align__(16) float g_G[NROWS*KK];       // [row][k] cosine scores
__device__ __align__(16) float g_beta[NROWS];       // softmax weights
__device__ __align__(16) float g_part[BB*NCH*PD];   // pooling partials

// ---- packed fp32x2 FMA (Blackwell FFMA2 path) ----
__device__ __forceinline__ void fma2(unsigned long long& d,
                                     unsigned long long a,
                                     unsigned long long b) {
    asm("fma.rn.f32x2 %0, %1, %2, %0;" : "+l"(d) : "l"(a), "l"(b));
}
__device__ __forceinline__ float sum2(unsigned long long v) {
    return __uint_as_float((unsigned)v) + __uint_as_float((unsigned)(v >> 32));
}
__device__ __forceinline__ unsigned s2u(const void* p) {
    unsigned a;
    asm("{ .reg .u64 t; cvta.to.shared.u64 t, %1; cvt.u32.u64 %0, t; }"
        : "=r"(a) : "l"(p));
    return a;
}
__device__ __forceinline__ void bulk_cp(unsigned dst, const void* src,
                                        unsigned bytes, unsigned mbar) {
    asm volatile(
        "cp.async.bulk.shared::cluster.global.mbarrier::complete_tx::bytes "
        "[%0], [%1], %2, [%3];"
        :: "r"(dst), "l"(src), "r"(bytes), "r"(mbar) : "memory");
}
__device__ __forceinline__ void mbar_wait(unsigned addr, unsigned parity) {
    asm volatile(
        "{\n\t.reg .pred P1;\n\t"
        "WAIT_%=: mbarrier.try_wait.parity.acquire.cta.shared::cta.b64 P1, [%0], %1, 0x989680;\n\t"
        "@P1 bra DONE_%=;\n\tbra WAIT_%=;\n\tDONE_%=:\n\t}"
        :: "r"(addr), "r"(parity) : "memory");
}
union F4U2 { float4 f; unsigned long long u[2]; };

// ============================================================
// K0: normalized label matrix -> two pair-pair-packed half images.
// Image h, layout [P=75][tx=16][ppL=2][kk=2][e=2]:
//   thread tx of half h covers labels k = h*32 + 2tx + kk; element
//   p = 4P + 2*ppL + e.  A thread's 32B per P = 2 consecutive LDG.128.
// ============================================================
__global__ void k0_prep(const float* __restrict__ C) {
    __shared__ float inv[KK];
    const int tid = threadIdx.x;   // 256
    if (tid < KK) {
        float s = 0.f;
        const float* row = C + tid * PD;
        for (int p = 0; p < PD; p++) s = fmaf(row[p], row[p], s);
        inv[tid] = 1.f / (sqrtf(s) + 0.001f);
    }
    __syncthreads();
    const int span = (2 * CH_IMG) / 4;
    const int base = blockIdx.x * span;
    for (int ii = tid; ii < span; ii += 256) {
        int i  = base + ii;
        int h  = i / CH_IMG;
        int r  = i - h * CH_IMG;
        int P  = r >> 7;
        int q  = r & 127;
        int tx = q >> 3;
        int w  = q & 7;
        int l  = w >> 2;
        int kk = (w >> 1) & 1;
        int e  = w & 1;
        int k  = h * 32 + tx * 2 + kk;
        int p  = 4 * P + 2 * l + e;
        g_ch2[i] = (k < KK) ? C[k * PD + p] * inv[k] : 0.f;
    }
}

// ============================================================
// K1: gathered cosine-score GEMM.
// Block: 64 rows x 32 labels (label half h = bid>>9).
// smem = gathered rows only (76.8 KB) -> 2 blocks/SM, 16 warps:
// bulk-copy prologue of one block overlaps mainloop of the other.
// B image (38.4 KB) read via LDG -> L1-resident (74 KB available).
// 256 threads: tx=tid&15 (2 labels), ty=tid>>4 (4 rows).
// Mainloop: 75 pp-pair iters, register double-buffered.
// ============================================================
__global__ void __launch_bounds__(256, 2)
k1_scores(const int* __restrict__ idx, const float* __restrict__ emb) {
    extern __shared__ float xs[];    // BM * XSS
    __shared__ float inv[BM];
    __shared__ __align__(8) unsigned long long s_mbar;

    const int tid  = threadIdx.x;
    const int lane = tid & 31;
    const int warp = tid >> 5;
    const int g    = blockIdx.x & 511;
    const int h    = blockIdx.x >> 9;
    const int row0 = g * BM;
    const unsigned mbar = s2u(&s_mbar);

    if (tid == 0) {
        asm volatile("mbarrier.init.shared.b64 [%0], %1;"
                     :: "r"(mbar), "r"(1u) : "memory");
    }
    __syncthreads();
    if (tid == 0)
        asm volatile("mbarrier.arrive.expect_tx.shared.b64 _, [%0], %1;"
                     :: "r"(mbar), "r"((unsigned)TOTAL_TX) : "memory");
    __syncthreads();
    if (tid < BM) {
        const char* src = (const char*)(emb + (size_t)idx[row0 + tid] * PD);
        bulk_cp(s2u(xs + tid * XSS), src, ROW_BYTES, mbar);
    }
    mbar_wait(mbar, 0);
    __syncthreads();

    // inverse norms (warp per row)
    for (int r = warp; r < BM; r += 8) {
        const float* xr = xs + r * XSS;
        float ss = 0.f;
        #pragma unroll
        for (int i = 0; i < 10; i++) {
            int p = lane + 32 * i;
            if (p < PD) { float v = xr[p]; ss = fmaf(v, v, ss); }
        }
        #pragma unroll
        for (int o = 16; o; o >>= 1) ss += __shfl_xor_sync(0xffffffffu, ss, o);
        if (lane == 0) inv[r] = 1.f / (sqrtf(ss) + 0.001f);
    }
    __syncthreads();

    const int tx = tid & 15;   // 2 labels
    const int ty = tid >> 4;   // 4 rows

    unsigned long long acc[4][2];
    #pragma unroll
    for (int i = 0; i < 4; i++) { acc[i][0] = 0ull; acc[i][1] = 0ull; }

    const float* aBase = xs + (ty * 4) * XSS;
    const float* bBase = g_ch2 + h * CH_IMG + tx * 8;   // 32B per P

    // ---- software-pipelined mainloop over P = 0..74 ----
    F4U2 aC[4], aN[4];
    ulonglong2 bC0, bC1, bN0, bN1;

    #pragma unroll
    for (int i = 0; i < 4; i++)
        aC[i].f = *(const float4*)(aBase + i * XSS);
    bC0 = __ldg((const ulonglong2*)bBase);          // pp even: k0,k1 pairs
    bC1 = __ldg((const ulonglong2*)(bBase + 4));    // pp odd

    #pragma unroll 1
    for (int P = 0; P < 74; P++) {
        const float* aP = aBase + 4 * (P + 1);
        const float* bP = bBase + 128 * (P + 1);
        #pragma unroll
        for (int i = 0; i < 4; i++)
            aN[i].f = *(const float4*)(aP + i * XSS);
        bN0 = __ldg((const ulonglong2*)bP);
        bN1 = __ldg((const ulonglong2*)(bP + 4));
        #pragma unroll
        for (int i = 0; i < 4; i++) {
            fma2(acc[i][0], aC[i].u[0], bC0.x);
            fma2(acc[i][1], aC[i].u[0], bC0.y);
            fma2(acc[i][0], aC[i].u[1], bC1.x);
            fma2(acc[i][1], aC[i].u[1], bC1.y);
        }
        #pragma unroll
        for (int i = 0; i < 4; i++) aC[i] = aN[i];
        bC0 = bN0; bC1 = bN1;
    }
    #pragma unroll
    for (int i = 0; i < 4; i++) {
        fma2(acc[i][0], aC[i].u[0], bC0.x);
        fma2(acc[i][1], aC[i].u[0], bC0.y);
        fma2(acc[i][0], aC[i].u[1], bC1.x);
        fma2(acc[i][1], aC[i].u[1], bC1.y);
    }

    // epilogue: scale by 1/(||x||+eps), store k<50
    #pragma unroll
    for (int i = 0; i < 4; i++) {
        int row = row0 + ty * 4 + i;
        float iv = inv[ty * 4 + i];
        float* gout = g_G + (size_t)row * KK;
        #pragma unroll
        for (int j = 0; j < 2; j++) {
            int k = h * 32 + tx * 2 + j;
            if (k < KK) gout[k] = sum2(acc[i][j]) * iv;
        }
    }
}

// ============================================================
// K2: per-batch conv(11) + relu + max-over-k + softmax over s.
// One block per b, 512 threads. Padded smem tile, stride 51.
// ============================================================
#define GST 51
#define GROWS (SS + 2*RR)   // 522

__global__ void __launch_bounds__(512, 1)
k2_attn(const float* __restrict__ cw, const float* __restrict__ cbp) {
    extern __shared__ float Gs[];   // GROWS * GST
    __shared__ float red1[16], red2[16];
    __shared__ float wloc[11];
    __shared__ float sc[3];         // [0]=conv_b, [1]=max, [2]=sum

    const int b = blockIdx.x, tid = threadIdx.x;
    if (tid < 11) wloc[tid] = cw[tid];
    if (tid == 16) sc[0] = cbp[0];

    for (int i = tid; i < RR * GST; i += 512) {
        Gs[i] = 0.f;
        Gs[(SS + RR) * GST + i] = 0.f;
    }
    const float* Gb = g_G + (size_t)b * SS * KK;
    for (int i = tid; i < SS * KK; i += 512) {
        int s = i / KK, k = i - s * KK;
        Gs[(s + RR) * GST + k] = Gb[i];
    }
    __syncthreads();

    const int s = tid;
    const float cbv = sc[0];
    float m = 0.f;   // relu >= 0
    for (int k = 0; k < KK; k++) {
        float v = cbv;
        const float* gp = Gs + s * GST + k;
        #pragma unroll
        for (int j = 0; j < 11; j++) v = fmaf(wloc[j], gp[j * GST], v);
        m = fmaxf(m, fmaxf(v, 0.f));
    }

    const int lane = tid & 31, warp = tid >> 5;
    float mx = m;
    #pragma unroll
    for (int o = 16; o; o >>= 1) mx = fmaxf(mx, __shfl_xor_sync(0xffffffffu, mx, o));
    if (lane == 0) red1[warp] = mx;
    __syncthreads();
    if (warp == 0) {
        float v = (lane < 16) ? red1[lane] : -1e30f;
        #pragma unroll
        for (int o = 8; o; o >>= 1) v = fmaxf(v, __shfl_xor_sync(0xffffffffu, v, o));
        if (lane == 0) sc[1] = v;
    }
    __syncthreads();
    float e = expf(m - sc[1]);
    float sum = e;
    #pragma unroll
    for (int o = 16; o; o >>= 1) sum += __shfl_xor_sync(0xffffffffu, sum, o);
    if (lane == 0) red2[warp] = sum;
    __syncthreads();
    if (warp == 0) {
        float v = (lane < 16) ? red2[lane] : 0.f;
        #pragma unroll
        for (int o = 8; o; o >>= 1) v += __shfl_xor_sync(0xffffffffu, v, o);
        if (lane == 0) sc[2] = v;
    }
    __syncthreads();
    g_beta[b * SS + s] = e / sc[2];
}

// ============================================================
// K3a: pooling partials. grid (8 chunks, 64 b), 320 threads,
// 64 s per block (measured-best config).
// ============================================================
__global__ void __launch_bounds__(320, 1)
k3a_pool(const int* __restrict__ idx, const float* __restrict__ emb) {
    __shared__ float sbeta[64];
    __shared__ int   sidx[64];
    const int cx = blockIdx.x, b = blockIdx.y, tid = threadIdx.x;
    const int s0 = b * SS + cx * 64;
    if (tid < 64) {
        sbeta[tid] = g_beta[s0 + tid];
        sidx[tid]  = idx[s0 + tid];
    }
    __syncthreads();
    if (tid < PD) {
        float a0 = 0.f, a1 = 0.f, a2 = 0.f, a3 = 0.f;
        #pragma unroll 4
        for (int s = 0; s < 64; s += 4) {
            a0 = fmaf(sbeta[s],     emb[(size_t)sidx[s]     * PD + tid], a0);
            a1 = fmaf(sbeta[s + 1], emb[(size_t)sidx[s + 1] * PD + tid], a1);
            a2 = fmaf(sbeta[s + 2], emb[(size_t)sidx[s + 2] * PD + tid], a2);
            a3 = fmaf(sbeta[s + 3], emb[(size_t)sidx[s + 3] * PD + tid], a3);
        }
        g_part[(b * NCH + cx) * PD + tid] = (a0 + a1) + (a2 + a3);
    }
}

// ============================================================
// K3b: combine partials + final GEMV out = pooled @ W2^T + b2.
// ============================================================
__global__ void __launch_bounds__(320, 4)
k3b_out(const float* __restrict__ W2, const float* __restrict__ b2,
        float* __restrict__ out) {
    __shared__ float pooled[PD];
    const int b = blockIdx.x, tid = threadIdx.x;
    if (tid < PD) {
        float s = 0.f;
        #pragma unroll
        for (int c = 0; c < NCH; c++) s += g_part[(b * NCH + c) * PD + tid];
        pooled[tid] = s * (1.0f / (float)SS);
    }
    __syncthreads();

    const int warp = tid >> 5, lane = tid & 31;  // 10 warps x 5 k
    #pragma unroll
    for (int kk = 0; kk < 5; kk++) {
        int k = warp * 5 + kk;
        float d = 0.f;
        for (int p = lane; p < PD; p += 32) d = fmaf(pooled[p], W2[k * PD + p], d);
        #pragma unroll
        for (int o = 16; o; o >>= 1) d += __shfl_xor_sync(0xffffffffu, d, o);
        if (lane == 0) out[b * KK + k] = d + b2[k];
    }
}

// ============================================================
extern "C" void kernel_launch(void* const* d_in, const int* in_sizes, int n_in,
                              void* d_out, int out_size) {
    const int*   idx    = (const int*)d_in[0];
    const float* emb    = (const float*)d_in[1];
    const float* C      = (const float*)d_in[2];
    const float* conv_w = (const float*)d_in[3];
    const float* conv_b = (const float*)d_in[4];
    const float* W2     = (const float*)d_in[5];
    const float* b2     = (const float*)d_in[6];
    float*       out    = (float*)d_out;

    const int sm1 = BM * XSS * (int)sizeof(float);              // 76.8 KB (2 blocks/SM)
    const int sm2 = GROWS * GST * (int)sizeof(float);           // ~106 KB
    cudaFuncSetAttribute(k1_scores, cudaFuncAttributeMaxDynamicSharedMemorySize, sm1);
    cudaFuncSetAttribute(k2_attn,   cudaFuncAttributeMaxDynamicSharedMemorySize, sm2);

    k0_prep<<<4, 256>>>(C);
    k1_scores<<<1024, 256, sm1>>>(idx, emb);
    k2_attn<<<BB, 512, sm2>>>(conv_w, conv_b);
    k3a_pool<<<dim3(NCH, BB), 320>>>(idx, emb);
    k3b_out<<<BB, 320>>>(W2, b2, out);
}

// round 15
// speedup vs baseline: 1.1444x; 1.1444x over previous
#include <cuda_runtime.h>
#include <math.h>

// Problem constants
#define BB 64
#define SS 512
#define PD 300       // feature dim
#define KK 50        // labels
#define RR 5
#define NROWS (BB*SS)        // 32768
#define TM 32                // rows per k1 tile
#define NTILES (NROWS/TM)    // 1024
#define NBLK 148             // persistent blocks (<= SM count)
#define XSS 300              // row stride in floats (1200B)
#define CH_ELEMS (150*64*2)  // 19200 packed chat floats (76800 B)
#define NCH 8                // k3 pooling chunks per batch

#define ROW_BYTES (PD*4)             // 1200
#define TILE_TX (TM*ROW_BYTES)       // 38400
#define CH_BYTES (CH_ELEMS*4)        // 76800

// Scratch (device globals; no runtime allocation allowed)
__device__ __align__(16) float g_chat2[CH_ELEMS];   // [pp=150][half=2][tx=16][q=4]
__device__ __align__(16) float g_G[NROWS*KK];       // [row][k] cosine scores
__device__ __align__(16) float g_beta[NROWS];       // softmax weights
__device__ __align__(16) float g_part[BB*NCH*PD];   // pooling partials

// ---- packed fp32x2 FMA (Blackwell FFMA2 path) ----
__device__ __forceinline__ void fma2(unsigned long long& d,
                                     unsigned long long a,
                                     unsigned long long b) {
    asm("fma.rn.f32x2 %0, %1, %2, %0;" : "+l"(d) : "l"(a), "l"(b));
}
__device__ __forceinline__ float sum2(unsigned long long v) {
    return __uint_as_float((unsigned)v) + __uint_as_float((unsigned)(v >> 32));
}
__device__ __forceinline__ unsigned s2u(const void* p) {
    unsigned a;
    asm("{ .reg .u64 t; cvta.to.shared.u64 t, %1; cvt.u32.u64 %0, t; }"
        : "=r"(a) : "l"(p));
    return a;
}
__device__ __forceinline__ void bulk_cp(unsigned dst, const void* src,
                                        unsigned bytes, unsigned mbar) {
    asm volatile(
        "cp.async.bulk.shared::cluster.global.mbarrier::complete_tx::bytes "
        "[%0], [%1], %2, [%3];"
        :: "r"(dst), "l"(src), "r"(bytes), "r"(mbar) : "memory");
}
__device__ __forceinline__ void mbar_wait(unsigned addr, unsigned parity) {
    asm volatile(
        "{\n\t.reg .pred P1;\n\t"
        "WAIT_%=: mbarrier.try_wait.parity.acquire.cta.shared::cta.b64 P1, [%0], %1, 0x989680;\n\t"
        "@P1 bra DONE_%=;\n\tbra WAIT_%=;\n\tDONE_%=:\n\t}"
        :: "r"(addr), "r"(parity) : "memory");
}
union F4U2 { float4 f; unsigned long long u[2]; };

// ============================================================
// K0: normalize label embeddings C -> conflict-free packed g_chat2.
// Per pp (512B row): half=0 holds k pairs {4tx, 4tx+1}, half=1 {4tx+2, 4tx+3};
// thread tx reads its 4 k-pairs as two LDS.128 at tx*16B (conflict-free).
// ============================================================
__global__ void k0_chat(const float* __restrict__ C) {
    __shared__ float inv[64];
    int tid = threadIdx.x;   // 256
    if (tid < 64) {
        float s = 0.f;
        if (tid < KK) {
            const float* row = C + tid * PD;
            for (int p = 0; p < PD; p++) s = fmaf(row[p], row[p], s);
            inv[tid] = 1.f / (sqrtf(s) + 0.001f);
        } else {
            inv[tid] = 0.f;
        }
    }
    __syncthreads();
    const int span = CH_ELEMS / 4;
    const int base = blockIdx.x * span;
    for (int ii = tid; ii < span; ii += 256) {
        int i    = base + ii;
        int pp   = i >> 7;
        int rem  = i & 127;
        int half = rem >> 6;
        int w    = rem & 63;
        int tx   = w >> 2;
        int q    = w & 3;
        int k    = 4 * tx + 2 * half + (q >> 1);
        int e    = q & 1;
        int p    = 2 * pp + e;
        float v = 0.f;
        if (k < KK) v = C[k * PD + p] * inv[k];
        g_chat2[i] = v;
    }
}

// ============================================================
// K1: persistent gathered cosine-score GEMM.
// 148 blocks x 256 threads, occ 1 (153.6 KB smem).
// Each block loops over tiles g = bid, bid+148, ... (32 rows each),
// ping-ponging two 38.4KB row buffers: tile j+2's bulk-gather is
// issued after compute(j), overlapping compute(j+1) -> gather hidden.
// chat (76.8 KB) bulk-copied once per block.
// Per tile: thread (tx,ty) computes 2 rows x 4 labels, fp32x2 FMA.
// ============================================================
__global__ void __launch_bounds__(256, 1)
k1_scores(const int* __restrict__ idx, const float* __restrict__ emb) {
    extern __shared__ float sm1[];
    float* ch = sm1;                    // CH_ELEMS floats
    float* buf0 = sm1 + CH_ELEMS;       // TM * XSS
    float* buf1 = buf0 + TM * XSS;      // TM * XSS
    __shared__ float inv[TM];
    __shared__ __align__(8) unsigned long long s_mbar[2];

    const int tid  = threadIdx.x;
    const int lane = tid & 31;
    const int warp = tid >> 5;
    const int bid  = blockIdx.x;
    const unsigned mb0 = s2u(&s_mbar[0]);
    const unsigned mb1 = s2u(&s_mbar[1]);
    float* bufs[2] = {buf0, buf1};

    const int nt = (NTILES - bid + NBLK - 1) / NBLK;   // tiles for this block

    if (tid == 0) {
        asm volatile("mbarrier.init.shared.b64 [%0], %1;" :: "r"(mb0), "r"(1u) : "memory");
        asm volatile("mbarrier.init.shared.b64 [%0], %1;" :: "r"(mb1), "r"(1u) : "memory");
    }
    __syncthreads();

    // prologue: issue tile 0 (+chat) and tile 1
    if (tid == 0)
        asm volatile("mbarrier.arrive.expect_tx.shared.b64 _, [%0], %1;"
                     :: "r"(mb0), "r"((unsigned)(TILE_TX + CH_BYTES)) : "memory");
    if (nt > 1 && tid == 1)
        asm volatile("mbarrier.arrive.expect_tx.shared.b64 _, [%0], %1;"
                     :: "r"(mb1), "r"((unsigned)TILE_TX) : "memory");
    __syncthreads();
    if (tid < TM) {
        const int g0 = bid;
        const char* src = (const char*)(emb + (size_t)idx[g0 * TM + tid] * PD);
        bulk_cp(s2u(buf0 + tid * XSS), src, ROW_BYTES, mb0);
    } else if (tid < TM + 8) {
        const int c = tid - TM;
        bulk_cp(s2u(ch) + (unsigned)c * (CH_BYTES / 8),
                (const char*)g_chat2 + c * (CH_BYTES / 8), CH_BYTES / 8, mb0);
    } else if (nt > 1 && tid >= 64 && tid < 64 + TM) {
        const int g1 = bid + NBLK;
        const int r = tid - 64;
        const char* src = (const char*)(emb + (size_t)idx[g1 * TM + r] * PD);
        bulk_cp(s2u(buf1 + r * XSS), src, ROW_BYTES, mb1);
    }

    const int tx = tid & 15;   // 4 labels
    const int ty = tid >> 4;   // 2 rows
    const float* bBase = ch + tx * 4;
    unsigned ph0 = 0, ph1 = 0;

    for (int j = 0; j < nt; j++) {
        const int i = j & 1;
        float* xb = bufs[i];
        const int g = bid + j * NBLK;

        // wait for this tile's rows (and chat when j==0)
        if (i == 0) { mbar_wait(mb0, ph0); ph0 ^= 1; }
        else        { mbar_wait(mb1, ph1); ph1 ^= 1; }

        // norms: warp w -> rows w*4..w*4+3
        for (int r = warp * 4; r < warp * 4 + 4; r++) {
            const float* xr = xb + r * XSS;
            float ss = 0.f;
            #pragma unroll
            for (int u = 0; u < 10; u++) {
                int p = lane + 32 * u;
                if (p < PD) { float v = xr[p]; ss = fmaf(v, v, ss); }
            }
            #pragma unroll
            for (int o = 16; o; o >>= 1) ss += __shfl_xor_sync(0xffffffffu, ss, o);
            if (lane == 0) inv[r] = 1.f / (sqrtf(ss) + 0.001f);
        }
        __syncthreads();

        // ---- mainloop: 2 rows x 4 labels, software-pipelined over 2pp ----
        unsigned long long acc[2][4];
        #pragma unroll
        for (int r = 0; r < 2; r++)
            #pragma unroll
            for (int c = 0; c < 4; c++) acc[r][c] = 0ull;

        const float* aBase = xb + (ty * 2) * XSS;
        F4U2 aC[2], aN[2];
        ulonglong2 bC[4], bN[4];
        #pragma unroll
        for (int r = 0; r < 2; r++)
            aC[r].f = *(const float4*)(aBase + r * XSS);
        bC[0] = *(const ulonglong2*)(bBase);
        bC[1] = *(const ulonglong2*)(bBase + 64);
        bC[2] = *(const ulonglong2*)(bBase + 128);
        bC[3] = *(const ulonglong2*)(bBase + 192);

        #pragma unroll 1
        for (int pp = 0; pp < 148; pp += 2) {
            const float* aP = aBase + 2 * (pp + 2);
            const float* bP = bBase + (pp + 2) * 128;
            #pragma unroll
            for (int r = 0; r < 2; r++)
                aN[r].f = *(const float4*)(aP + r * XSS);
            bN[0] = *(const ulonglong2*)(bP);
            bN[1] = *(const ulonglong2*)(bP + 64);
            bN[2] = *(const ulonglong2*)(bP + 128);
            bN[3] = *(const ulonglong2*)(bP + 192);
            #pragma unroll
            for (int r = 0; r < 2; r++) {
                fma2(acc[r][0], aC[r].u[0], bC[0].x);
                fma2(acc[r][1], aC[r].u[0], bC[0].y);
                fma2(acc[r][2], aC[r].u[0], bC[1].x);
                fma2(acc[r][3], aC[r].u[0], bC[1].y);
                fma2(acc[r][0], aC[r].u[1], bC[2].x);
                fma2(acc[r][1], aC[r].u[1], bC[2].y);
                fma2(acc[r][2], aC[r].u[1], bC[3].x);
                fma2(acc[r][3], aC[r].u[1], bC[3].y);
            }
            #pragma unroll
            for (int r = 0; r < 2; r++) aC[r] = aN[r];
            #pragma unroll
            for (int c = 0; c < 4; c++) bC[c] = bN[c];
        }
        #pragma unroll
        for (int r = 0; r < 2; r++) {
            fma2(acc[r][0], aC[r].u[0], bC[0].x);
            fma2(acc[r][1], aC[r].u[0], bC[0].y);
            fma2(acc[r][2], aC[r].u[0], bC[1].x);
            fma2(acc[r][3], aC[r].u[0], bC[1].y);
            fma2(acc[r][0], aC[r].u[1], bC[2].x);
            fma2(acc[r][1], aC[r].u[1], bC[2].y);
            fma2(acc[r][2], aC[r].u[1], bC[3].x);
            fma2(acc[r][3], aC[r].u[1], bC[3].y);
        }

        // epilogue: scale + store
        #pragma unroll
        for (int r = 0; r < 2; r++) {
            const int lr = ty * 2 + r;
            const int row = g * TM + lr;
            const float iv = inv[lr];
            float* gout = g_G + (size_t)row * KK;
            #pragma unroll
            for (int c = 0; c < 4; c++) {
                int k = tx * 4 + c;
                if (k < KK) gout[k] = sum2(acc[r][c]) * iv;
            }
        }
        __syncthreads();   // all warps done with buf[i] and inv

        // issue tile j+2 into buf[i] (overlaps compute of tile j+1)
        const int gnext = g + 2 * NBLK;
        if (j + 2 < nt) {
            if (tid == 0)
                asm volatile("mbarrier.arrive.expect_tx.shared.b64 _, [%0], %1;"
                             :: "r"(i == 0 ? mb0 : mb1), "r"((unsigned)TILE_TX) : "memory");
            __syncwarp();
            if (tid < TM) {
                const char* src = (const char*)(emb + (size_t)idx[gnext * TM + tid] * PD);
                bulk_cp(s2u(xb + tid * XSS), src, ROW_BYTES, i == 0 ? mb0 : mb1);
            }
        }
    }
}

// ============================================================
// K2: per-batch conv(11) + relu + max-over-k + softmax over s.
// One block per b, 512 threads. Padded smem tile, stride 51.
// ============================================================
#define GST 51
#define GROWS (SS + 2*RR)   // 522

__global__ void __launch_bounds__(512, 1)
k2_attn(const float* __restrict__ cw, const float* __restrict__ cbp) {
    extern __shared__ float Gs[];   // GROWS * GST
    __shared__ float red1[16], red2[16];
    __shared__ float wloc[11];
    __shared__ float sc[3];         // [0]=conv_b, [1]=max, [2]=sum

    const int b = blockIdx.x, tid = threadIdx.x;
    if (tid < 11) wloc[tid] = cw[tid];
    if (tid == 16) sc[0] = cbp[0];

    for (int i = tid; i < RR * GST; i += 512) {
        Gs[i] = 0.f;
        Gs[(SS + RR) * GST + i] = 0.f;
    }
    const float* Gb = g_G + (size_t)b * SS * KK;
    for (int i = tid; i < SS * KK; i += 512) {
        int s = i / KK, k = i - s * KK;
        Gs[(s + RR) * GST + k] = Gb[i];
    }
    __syncthreads();

    const int s = tid;
    const float cbv = sc[0];
    float m = 0.f;   // relu >= 0
    for (int k = 0; k < KK; k++) {
        float v = cbv;
        const float* gp = Gs + s * GST + k;
        #pragma unroll
        for (int j = 0; j < 11; j++) v = fmaf(wloc[j], gp[j * GST], v);
        m = fmaxf(m, fmaxf(v, 0.f));
    }

    const int lane = tid & 31, warp = tid >> 5;
    float mx = m;
    #pragma unroll
    for (int o = 16; o; o >>= 1) mx = fmaxf(mx, __shfl_xor_sync(0xffffffffu, mx, o));
    if (lane == 0) red1[warp] = mx;
    __syncthreads();
    if (warp == 0) {
        float v = (lane < 16) ? red1[lane] : -1e30f;
        #pragma unroll
        for (int o = 8; o; o >>= 1) v = fmaxf(v, __shfl_xor_sync(0xffffffffu, v, o));
        if (lane == 0) sc[1] = v;
    }
    __syncthreads();
    float e = expf(m - sc[1]);
    float sum = e;
    #pragma unroll
    for (int o = 16; o; o >>= 1) sum += __shfl_xor_sync(0xffffffffu, sum, o);
    if (lane == 0) red2[warp] = sum;
    __syncthreads();
    if (warp == 0) {
        float v = (lane < 16) ? red2[lane] : 0.f;
        #pragma unroll
        for (int o = 8; o; o >>= 1) v += __shfl_xor_sync(0xffffffffu, v, o);
        if (lane == 0) sc[2] = v;
    }
    __syncthreads();
    g_beta[b * SS + s] = e / sc[2];
}

// ============================================================
// K3a: pooling partials. grid (8 chunks, 64 b), 320 threads,
// 64 s per block (measured-best config).
// ============================================================
__global__ void __launch_bounds__(320, 1)
k3a_pool(const int* __restrict__ idx, const float* __restrict__ emb) {
    __shared__ float sbeta[64];
    __shared__ int   sidx[64];
    const int cx = blockIdx.x, b = blockIdx.y, tid = threadIdx.x;
    const int s0 = b * SS + cx * 64;
    if (tid < 64) {
        sbeta[tid] = g_beta[s0 + tid];
        sidx[tid]  = idx[s0 + tid];
    }
    __syncthreads();
    if (tid < PD) {
        float a0 = 0.f, a1 = 0.f, a2 = 0.f, a3 = 0.f;
        #pragma unroll 4
        for (int s = 0; s < 64; s += 4) {
            a0 = fmaf(sbeta[s],     emb[(size_t)sidx[s]     * PD + tid], a0);
            a1 = fmaf(sbeta[s + 1], emb[(size_t)sidx[s + 1] * PD + tid], a1);
            a2 = fmaf(sbeta[s + 2], emb[(size_t)sidx[s + 2] * PD + tid], a2);
            a3 = fmaf(sbeta[s + 3], emb[(size_t)sidx[s + 3] * PD + tid], a3);
        }
        g_part[(b * NCH + cx) * PD + tid] = (a0 + a1) + (a2 + a3);
    }
}

// ============================================================
// K3b: combine partials + final GEMV out = pooled @ W2^T + b2.
// ============================================================
__global__ void __launch_bounds__(320, 4)
k3b_out(const float* __restrict__ W2, const float* __restrict__ b2,
        float* __restrict__ out) {
    __shared__ float pooled[PD];
    const int b = blockIdx.x, tid = threadIdx.x;
    if (tid < PD) {
        float s = 0.f;
        #pragma unroll
        for (int c = 0; c < NCH; c++) s += g_part[(b * NCH + c) * PD + tid];
        pooled[tid] = s * (1.0f / (float)SS);
    }
    __syncthreads();

    const int warp = tid >> 5, lane = tid & 31;  // 10 warps x 5 k
    #pragma unroll
    for (int kk = 0; kk < 5; kk++) {
        int k = warp * 5 + kk;
        float d = 0.f;
        for (int p = lane; p < PD; p += 32) d = fmaf(pooled[p], W2[k * PD + p], d);
        #pragma unroll
        for (int o = 16; o; o >>= 1) d += __shfl_xor_sync(0xffffffffu, d, o);
        if (lane == 0) out[b * KK + k] = d + b2[k];
    }
}

// ============================================================
extern "C" void kernel_launch(void* const* d_in, const int* in_sizes, int n_in,
                              void* d_out, int out_size) {
    const int*   idx    = (const int*)d_in[0];
    const float* emb    = (const float*)d_in[1];
    const float* C      = (const float*)d_in[2];
    const float* conv_w = (const float*)d_in[3];
    const float* conv_b = (const float*)d_in[4];
    const float* W2     = (const float*)d_in[5];
    const float* b2     = (const float*)d_in[6];
    float*       out    = (float*)d_out;

    const int sm1 = (CH_ELEMS + 2 * TM * XSS) * (int)sizeof(float);  // 153.6 KB
    const int sm2 = GROWS * GST * (int)sizeof(float);                // ~106 KB
    cudaFuncSetAttribute(k1_scores, cudaFuncAttributeMaxDynamicSharedMemorySize, sm1);
    cudaFuncSetAttribute(k2_attn,   cudaFuncAttributeMaxDynamicSharedMemorySize, sm2);

    k0_chat<<<4, 256>>>(C);
    k1_scores<<<NBLK, 256, sm1>>>(idx, emb);
    k2_attn<<<BB, 512, sm2>>>(conv_w, conv_b);
    k3a_pool<<<dim3(NCH, BB), 320>>>(idx, emb);
    k3b_out<<<BB, 320>>>(W2, b2, out);
}

// round 16
// speedup vs baseline: 1.3108x; 1.1454x over previous
#include <cuda_runtime.h>
#include <math.h>

// Problem constants
#define BB 64
#define SS 512
#define PD 300       // feature dim
#define KK 50        // labels
#define KP 64        // padded labels
#define RR 5
#define NROWS (BB*SS)        // 32768
#define BM 64                // rows per K1 block
#define XSS 300              // xs row stride in floats (1200B)
#define CH_ELEMS (150*KP*2)  // 19200 pair-packed chat floats (76800 B)
#define NCH 8                // k3 pooling chunks per batch

#define ROW_BYTES (PD*4)               // 1200
#define TOTAL_TX (CH_ELEMS*4 + BM*ROW_BYTES)   // 153600
#define CH_BYTES (CH_ELEMS*4)          // 76800

// Scratch (device globals; no runtime allocation allowed)
__device__ __align__(16) float g_inv[KP];           // label inverse norms
__device__ __align__(16) float g_chat2[CH_ELEMS];   // [pp=150][half=2][tx=16][q=4]
__device__ __align__(16) float g_G[NROWS*KK];       // [row][k] cosine scores
__device__ __align__(16) float g_beta[NROWS];       // softmax weights
__device__ __align__(16) float g_part[BB*NCH*PD];   // pooling partials

// ---- packed fp32x2 FMA (Blackwell FFMA2 path) ----
__device__ __forceinline__ void fma2(unsigned long long& d,
                                     unsigned long long a,
                                     unsigned long long b) {
    asm("fma.rn.f32x2 %0, %1, %2, %0;" : "+l"(d) : "l"(a), "l"(b));
}
__device__ __forceinline__ float sum2(unsigned long long v) {
    return __uint_as_float((unsigned)v) + __uint_as_float((unsigned)(v >> 32));
}
__device__ __forceinline__ unsigned s2u(const void* p) {
    unsigned a;
    asm("{ .reg .u64 t; cvta.to.shared.u64 t, %1; cvt.u32.u64 %0, t; }"
        : "=r"(a) : "l"(p));
    return a;
}
__device__ __forceinline__ void bulk_cp(unsigned dst, const void* src,
                                        unsigned bytes, unsigned mbar) {
    asm volatile(
        "cp.async.bulk.shared::cluster.global.mbarrier::complete_tx::bytes "
        "[%0], [%1], %2, [%3];"
        :: "r"(dst), "l"(src), "r"(bytes), "r"(mbar) : "memory");
}
__device__ __forceinline__ void mbar_wait(unsigned addr, unsigned parity) {
    asm volatile(
        "{\n\t.reg .pred P1;\n\t"
        "WAIT_%=: mbarrier.try_wait.parity.acquire.cta.shared::cta.b64 P1, [%0], %1, 0x989680;\n\t"
        "@P1 bra DONE_%=;\n\tbra WAIT_%=;\n\tDONE_%=:\n\t}"
        :: "r"(addr), "r"(parity) : "memory");
}
union F4U2 { float4 f; unsigned long long u[2]; };

// ============================================================
// K0a: label inverse norms -> g_inv. (split from k0 so that k1 is
// the 4th launch and gets captured by the fixed ncu window)
// ============================================================
__global__ void k0a_norms(const float* __restrict__ C) {
    const int k = threadIdx.x;   // 64
    float v = 0.f;
    if (k < KK) {
        float s = 0.f;
        const float* row = C + k * PD;
        for (int p = 0; p < PD; p++) s = fmaf(row[p], row[p], s);
        v = 1.f / (sqrtf(s) + 0.001f);
    }
    g_inv[k] = v;
}

// ============================================================
// K0b/K0c: pack normalized C into g_chat2 (each does half).
// Per pp (512B row): half=0 holds k pairs {4tx, 4tx+1}, half=1 {4tx+2, 4tx+3};
// thread tx reads its 4 k-pairs as two LDS.128 at tx*16B (conflict-free).
// ============================================================
__device__ __forceinline__ void pack_span(const float* C, int base, int span) {
    const int tid = threadIdx.x;
    for (int ii = blockIdx.x * 256 + tid; ii < span; ii += 512) {
        int i    = base + ii;
        int pp   = i >> 7;
        int rem  = i & 127;
        int half = rem >> 6;
        int w    = rem & 63;
        int tx   = w >> 2;
        int q    = w & 3;
        int k    = 4 * tx + 2 * half + (q >> 1);
        int e    = q & 1;
        int p    = 2 * pp + e;
        float v = 0.f;
        if (k < KK) v = C[k * PD + p] * g_inv[k];
        g_chat2[i] = v;
    }
}
__global__ void k0b_pack(const float* __restrict__ C) {
    pack_span(C, 0, CH_ELEMS / 2);
}
__global__ void k0c_pack(const float* __restrict__ C) {
    pack_span(C, CH_ELEMS / 2, CH_ELEMS / 2);
}

// ============================================================
// K1: gathered cosine-score GEMM (byte-identical to the 80.6us best).
// Block: 64 rows x 64 k, 256 threads, 4x4 tile/thread.
// Staging via cp.async.bulk; mainloop software-pipelined fp32x2.
// ============================================================
__global__ void __launch_bounds__(256, 1)
k1_scores(const int* __restrict__ idx, const float* __restrict__ emb) {
    extern __shared__ float sm1[];
    float* ch = sm1;                 // CH_ELEMS floats
    float* xs = sm1 + CH_ELEMS;      // BM * XSS floats
    __shared__ float inv[BM];
    __shared__ __align__(8) unsigned long long s_mbar;

    const int tid  = threadIdx.x;
    const int lane = tid & 31;
    const int warp = tid >> 5;
    const int row0 = blockIdx.x * BM;
    const unsigned mbar = s2u(&s_mbar);

    if (tid == 0)
        asm volatile("mbarrier.init.shared.b64 [%0], %1;"
                     :: "r"(mbar), "r"(1u) : "memory");
    __syncthreads();
    if (tid == 0)
        asm volatile("mbarrier.arrive.expect_tx.shared.b64 _, [%0], %1;"
                     :: "r"(mbar), "r"((unsigned)TOTAL_TX) : "memory");
    __syncthreads();

    // issue bulk copies: gather rows (tid<64) + chat chunks (tid 64..71)
    if (tid < BM) {
        const char* src = (const char*)(emb + (size_t)idx[row0 + tid] * PD);
        bulk_cp(s2u(xs + tid * XSS), src, ROW_BYTES, mbar);
    } else if (tid < BM + 8) {
        const int c = tid - BM;
        bulk_cp(s2u(ch) + (unsigned)c * (CH_BYTES / 8),
                (const char*)g_chat2 + c * (CH_BYTES / 8),
                CH_BYTES / 8, mbar);
    }
    mbar_wait(mbar, 0);
    __syncthreads();

    // inverse norms (warp per row)
    for (int r = warp; r < BM; r += 8) {
        const float* xr = xs + r * XSS;
        float ss = 0.f;
        #pragma unroll
        for (int i = 0; i < 10; i++) {
            int p = lane + 32 * i;
            if (p < PD) { float v = xr[p]; ss = fmaf(v, v, ss); }
        }
        #pragma unroll
        for (int o = 16; o; o >>= 1) ss += __shfl_xor_sync(0xffffffffu, ss, o);
        if (lane == 0) inv[r] = 1.f / (sqrtf(ss) + 0.001f);
    }
    __syncthreads();

    const int tx = tid & 15;   // k direction (4 k each)
    const int ty = tid >> 4;   // row direction (4 rows each)

    unsigned long long acc[4][4];
    #pragma unroll
    for (int i = 0; i < 4; i++)
        #pragma unroll
        for (int j = 0; j < 4; j++) acc[i][j] = 0ull;

    const float* aBase = xs + (ty * 4) * XSS;
    const float* bBase = ch + tx * 4;   // 16B-stride chunks, conflict-free

    // ---- software-pipelined mainloop: 2 p-pairs per iteration ----
    F4U2 aC[4], aN[4];
    ulonglong2 bC[4], bN[4];

    #pragma unroll
    for (int i = 0; i < 4; i++)
        aC[i].f = *(const float4*)(aBase + i * XSS);
    bC[0] = *(const ulonglong2*)(bBase);
    bC[1] = *(const ulonglong2*)(bBase + 64);
    bC[2] = *(const ulonglong2*)(bBase + 128);
    bC[3] = *(const ulonglong2*)(bBase + 192);

    #pragma unroll 1
    for (int pp = 0; pp < 148; pp += 2) {
        const float* aP = aBase + 2 * (pp + 2);
        const float* bP = bBase + (pp + 2) * 128;
        #pragma unroll
        for (int i = 0; i < 4; i++)
            aN[i].f = *(const float4*)(aP + i * XSS);
        bN[0] = *(const ulonglong2*)(bP);
        bN[1] = *(const ulonglong2*)(bP + 64);
        bN[2] = *(const ulonglong2*)(bP + 128);
        bN[3] = *(const ulonglong2*)(bP + 192);
        #pragma unroll
        for (int i = 0; i < 4; i++) {
            fma2(acc[i][0], aC[i].u[0], bC[0].x);
            fma2(acc[i][1], aC[i].u[0], bC[0].y);
            fma2(acc[i][2], aC[i].u[0], bC[1].x);
            fma2(acc[i][3], aC[i].u[0], bC[1].y);
        }
        #pragma unroll
        for (int i = 0; i < 4; i++) {
            fma2(acc[i][0], aC[i].u[1], bC[2].x);
            fma2(acc[i][1], aC[i].u[1], bC[2].y);
            fma2(acc[i][2], aC[i].u[1], bC[3].x);
            fma2(acc[i][3], aC[i].u[1], bC[3].y);
        }
        #pragma unroll
        for (int i = 0; i < 4; i++) aC[i] = aN[i];
        #pragma unroll
        for (int i = 0; i < 4; i++) bC[i] = bN[i];
    }
    #pragma unroll
    for (int i = 0; i < 4; i++) {
        fma2(acc[i][0], aC[i].u[0], bC[0].x);
        fma2(acc[i][1], aC[i].u[0], bC[0].y);
        fma2(acc[i][2], aC[i].u[0], bC[1].x);
        fma2(acc[i][3], aC[i].u[0], bC[1].y);
    }
    #pragma unroll
    for (int i = 0; i < 4; i++) {
        fma2(acc[i][0], aC[i].u[1], bC[2].x);
        fma2(acc[i][1], aC[i].u[1], bC[2].y);
        fma2(acc[i][2], aC[i].u[1], bC[3].x);
        fma2(acc[i][3], aC[i].u[1], bC[3].y);
    }

    // epilogue: scale by 1/(||x||+eps), store k<50
    #pragma unroll
    for (int i = 0; i < 4; i++) {
        int row = row0 + ty * 4 + i;
        float iv = inv[ty * 4 + i];
        float* gout = g_G + (size_t)row * KK;
        #pragma unroll
        for (int j = 0; j < 4; j++) {
            int k = tx * 4 + j;
            if (k < KK) gout[k] = sum2(acc[i][j]) * iv;
        }
    }
}

// ============================================================
// K2: per-batch conv(11) + relu + max-over-k + softmax over s.
// One block per b, 512 threads. Padded smem tile, stride 51.
// ============================================================
#define GST 51
#define GROWS (SS + 2*RR)   // 522

__global__ void __launch_bounds__(512, 1)
k2_attn(const float* __restrict__ cw, const float* __restrict__ cbp) {
    extern __shared__ float Gs[];   // GROWS * GST
    __shared__ float red1[16], red2[16];
    __shared__ float wloc[11];
    __shared__ float sc[3];         // [0]=conv_b, [1]=max, [2]=sum

    const int b = blockIdx.x, tid = threadIdx.x;
    if (tid < 11) wloc[tid] = cw[tid];
    if (tid == 16) sc[0] = cbp[0];

    for (int i = tid; i < RR * GST; i += 512) {
        Gs[i] = 0.f;
        Gs[(SS + RR) * GST + i] = 0.f;
    }
    const float* Gb = g_G + (size_t)b * SS * KK;
    for (int i = tid; i < SS * KK; i += 512) {
        int s = i / KK, k = i - s * KK;
        Gs[(s + RR) * GST + k] = Gb[i];
    }
    __syncthreads();

    const int s = tid;
    const float cbv = sc[0];
    float m = 0.f;   // relu >= 0
    for (int k = 0; k < KK; k++) {
        float v = cbv;
        const float* gp = Gs + s * GST + k;
        #pragma unroll
        for (int j = 0; j < 11; j++) v = fmaf(wloc[j], gp[j * GST], v);
        m = fmaxf(m, fmaxf(v, 0.f));
    }

    const int lane = tid & 31, warp = tid >> 5;
    float mx = m;
    #pragma unroll
    for (int o = 16; o; o >>= 1) mx = fmaxf(mx, __shfl_xor_sync(0xffffffffu, mx, o));
    if (lane == 0) red1[warp] = mx;
    __syncthreads();
    if (warp == 0) {
        float v = (lane < 16) ? red1[lane] : -1e30f;
        #pragma unroll
        for (int o = 8; o; o >>= 1) v = fmaxf(v, __shfl_xor_sync(0xffffffffu, v, o));
        if (lane == 0) sc[1] = v;
    }
    __syncthreads();
    float e = expf(m - sc[1]);
    float sum = e;
    #pragma unroll
    for (int o = 16; o; o >>= 1) sum += __shfl_xor_sync(0xffffffffu, sum, o);
    if (lane == 0) red2[warp] = sum;
    __syncthreads();
    if (warp == 0) {
        float v = (lane < 16) ? red2[lane] : 0.f;
        #pragma unroll
        for (int o = 8; o; o >>= 1) v += __shfl_xor_sync(0xffffffffu, v, o);
        if (lane == 0) sc[2] = v;
    }
    __syncthreads();
    g_beta[b * SS + s] = e / sc[2];
}

// ============================================================
// K3a: pooling partials. grid (8 chunks, 64 b), 320 threads,
// 64 s per block (measured-best config).
// ============================================================
__global__ void __launch_bounds__(320, 1)
k3a_pool(const int* __restrict__ idx, const float* __restrict__ emb) {
    __shared__ float sbeta[64];
    __shared__ int   sidx[64];
    const int cx = blockIdx.x, b = blockIdx.y, tid = threadIdx.x;
    const int s0 = b * SS + cx * 64;
    if (tid < 64) {
        sbeta[tid] = g_beta[s0 + tid];
        sidx[tid]  = idx[s0 + tid];
    }
    __syncthreads();
    if (tid < PD) {
        float a0 = 0.f, a1 = 0.f, a2 = 0.f, a3 = 0.f;
        #pragma unroll 4
        for (int s = 0; s < 64; s += 4) {
            a0 = fmaf(sbeta[s],     emb[(size_t)sidx[s]     * PD + tid], a0);
            a1 = fmaf(sbeta[s + 1], emb[(size_t)sidx[s + 1] * PD + tid], a1);
            a2 = fmaf(sbeta[s + 2], emb[(size_t)sidx[s + 2] * PD + tid], a2);
            a3 = fmaf(sbeta[s + 3], emb[(size_t)sidx[s + 3] * PD + tid], a3);
        }
        g_part[(b * NCH + cx) * PD + tid] = (a0 + a1) + (a2 + a3);
    }
}

// ============================================================
// K3b: combine partials + final GEMV out = pooled @ W2^T + b2.
// ============================================================
__global__ void __launch_bounds__(320, 4)
k3b_out(const float* __restrict__ W2, const float* __restrict__ b2,
        float* __restrict__ out) {
    __shared__ float pooled[PD];
    const int b = blockIdx.x, tid = threadIdx.x;
    if (tid < PD) {
        float s = 0.f;
        #pragma unroll
        for (int c = 0; c < NCH; c++) s += g_part[(b * NCH + c) * PD + tid];
        pooled[tid] = s * (1.0f / (float)SS);
    }
    __syncthreads();

    const int warp = tid >> 5, lane = tid & 31;  // 10 warps x 5 k
    #pragma unroll
    for (int kk = 0; kk < 5; kk++) {
        int k = warp * 5 + kk;
        float d = 0.f;
        for (int p = lane; p < PD; p += 32) d = fmaf(pooled[p], W2[k * PD + p], d);
        #pragma unroll
        for (int o = 16; o; o >>= 1) d += __shfl_xor_sync(0xffffffffu, d, o);
        if (lane == 0) out[b * KK + k] = d + b2[k];
    }
}

// ============================================================
extern "C" void kernel_launch(void* const* d_in, const int* in_sizes, int n_in,
                              void* d_out, int out_size) {
    const int*   idx    = (const int*)d_in[0];
    const float* emb    = (const float*)d_in[1];
    const float* C      = (const float*)d_in[2];
    const float* conv_w = (const float*)d_in[3];
    const float* conv_b = (const float*)d_in[4];
    const float* W2     = (const float*)d_in[5];
    const float* b2     = (const float*)d_in[6];
    float*       out    = (float*)d_out;

    const int sm1 = (CH_ELEMS + BM * XSS) * (int)sizeof(float);   // ~152 KB
    const int sm2 = GROWS * GST * (int)sizeof(float);             // ~106 KB
    cudaFuncSetAttribute(k1_scores, cudaFuncAttributeMaxDynamicSharedMemorySize, sm1);
    cudaFuncSetAttribute(k2_attn,   cudaFuncAttributeMaxDynamicSharedMemorySize, sm2);

    // k1 is deliberately the 4th launch: the fixed ncu window (-s 5 -c 1)
    // has captured the 4th kernel of the pipeline in every prior round.
    k0a_norms<<<1, 64>>>(C);
    k0b_pack<<<2, 256>>>(C);
    k0c_pack<<<2, 256>>>(C);
    k1_scores<<<NROWS / BM, 256, sm1>>>(idx, emb);
    k2_attn<<<BB, 512, sm2>>>(conv_w, conv_b);
    k3a_pool<<<dim3(NCH, BB), 320>>>(idx, emb);
    k3b_out<<<BB, 320>>>(W2, b2, out);
}